// round 2
// baseline (speedup 1.0000x reference)
#include <cuda_runtime.h>

#define HH 150
#define WW 200
#define NN (HH*WW)          // 30000
#define NPAD 30720          // 30 * 1024, padded loop bound
#define KK 1024
#define PP 5
#define SEG (PP*(KK+1))     // 5125
#define CAP 8192
#define NTHREADS 1024

// ---------------------------------------------------------------------------
// Exact k-th smallest (0-based) among the n floats in smem buf (all > 0).
// MSB-first 8-bit radix select; positive-float bit pattern is order-preserving.
// Block-collective; all threads return the same value.
// NOTE: leading __syncthreads() protects readers of the PREVIOUS call's
// result from tid 0's re-initialization (this race caused Round 1's failure).
// ---------------------------------------------------------------------------
__device__ __forceinline__ float kth_from_buf(const float* buf, int n, int k,
                                              int* hist, unsigned* sh_prefix,
                                              int* sh_k, int tid) {
    __syncthreads();                       // fence vs. previous call's readers
    if (tid == 0) { *sh_prefix = 0u; *sh_k = k; }
    __syncthreads();
    for (int shift = 24; shift >= 0; shift -= 8) {
        for (int j = tid; j < 256; j += NTHREADS) hist[j] = 0;
        __syncthreads();
        unsigned prefix = *sh_prefix;
        for (int i = tid; i < n; i += NTHREADS) {
            unsigned key = __float_as_uint(buf[i]);
            bool match = (shift == 24) ||
                         ((key >> (shift + 8)) == (prefix >> (shift + 8)));
            if (match) atomicAdd(&hist[(key >> shift) & 255], 1);
        }
        __syncthreads();
        if (tid == 0) {
            int kk = *sh_k, cum = 0, bsel = 0;
            for (int bb = 0; bb < 256; bb++) {
                int h = hist[bb];
                if (kk < cum + h) { kk -= cum; bsel = bb; break; }
                cum += h;
            }
            *sh_k = kk;
            *sh_prefix = prefix | ((unsigned)bsel << shift);
        }
        __syncthreads();
    }
    return __uint_as_float(*sh_prefix);
}

// Fallback: same radix select re-reading depth/indicator from global.
// Only used when n > CAP (never for this input shape, but keeps the kernel
// unconditionally correct).
__device__ __forceinline__ float kth_from_gmem(const float* __restrict__ depth,
                                               const float* __restrict__ ind,
                                               int pid, int k,
                                               int* hist, unsigned* sh_prefix,
                                               int* sh_k, int tid) {
    __syncthreads();
    if (tid == 0) { *sh_prefix = 0u; *sh_k = k; }
    __syncthreads();
    for (int shift = 24; shift >= 0; shift -= 8) {
        for (int j = tid; j < 256; j += NTHREADS) hist[j] = 0;
        __syncthreads();
        unsigned prefix = *sh_prefix;
        for (int i = tid; i < NN; i += NTHREADS) {
            float d = depth[i];
            bool v = (__float2int_rn(ind[i]) == pid) && (d > 3.0f);
            if (v) {
                unsigned key = __float_as_uint(d);
                bool match = (shift == 24) ||
                             ((key >> (shift + 8)) == (prefix >> (shift + 8)));
                if (match) atomicAdd(&hist[(key >> shift) & 255], 1);
            }
        }
        __syncthreads();
        if (tid == 0) {
            int kk = *sh_k, cum = 0, bsel = 0;
            for (int bb = 0; bb < 256; bb++) {
                int h = hist[bb];
                if (kk < cum + h) { kk -= cum; bsel = bb; break; }
                cum += h;
            }
            *sh_k = kk;
            *sh_prefix = prefix | ((unsigned)bsel << shift);
        }
        __syncthreads();
    }
    return __uint_as_float(*sh_prefix);
}

// ---------------------------------------------------------------------------
// One CTA per (batch, person). Phases:
//   0. precompute camera-ray table (double divide once, not per point)
//   1. gather valid depths to smem (warp-aggregated compaction)
//   2. exact q1/q3 via radix select -> IQR bounds
//   3. zero output slice; raster-order block scan; scatter first K kept points
// ---------------------------------------------------------------------------
__global__ void __launch_bounds__(NTHREADS)
pc_kernel(const float* __restrict__ in, float* __restrict__ out) {
    const int blk = blockIdx.x;
    const int b = blk / PP;
    const int p = blk % PP;
    const int pid = p + 1;
    const int tid = threadIdx.x;

    const float* depth = in + (size_t)b * 3 * NN;
    const float* ind   = depth + NN;

    __shared__ float buf[CAP];
    __shared__ float xcam[WW];
    __shared__ float ycam[HH];
    __shared__ int   hist[256];
    __shared__ int   warp_sums[32];
    __shared__ int   sh_cnt;
    __shared__ unsigned sh_prefix;
    __shared__ int   sh_k;

    // ---- Phase 0: ray tables (float64 math, matching NumPy promotion) ----
    {
        const double PI = 3.14159265358979323846;
        const double fxd = 200.0 / (2.0 * tan(81.0 * PI / 180.0 / 2.0));
        const double fyd = 150.0 / (2.0 * tan(59.0 * PI / 180.0 / 2.0));
        if (tid < WW) xcam[tid] = (float)(((double)tid - 100.0) / fxd);
        if (tid < HH) ycam[tid] = (float)(((double)tid - 75.0) / fyd);
    }
    if (tid == 0) sh_cnt = 0;
    __syncthreads();

    // ---- Phase 1: gather valid depths into smem -------------------------
    for (int i = tid; i < NPAD; i += NTHREADS) {
        float d = 0.0f;
        bool v = false;
        if (i < NN) {
            d = depth[i];
            v = (__float2int_rn(ind[i]) == pid) && (d > 3.0f);
        }
        unsigned bal = __ballot_sync(0xffffffffu, v);
        if (v) {
            int lane = tid & 31;
            int leader = __ffs(bal) - 1;
            int base;
            if (lane == leader) base = atomicAdd(&sh_cnt, __popc(bal));
            base = __shfl_sync(bal, base, leader);
            int pos = base + __popc(bal & ((1u << lane) - 1u));
            if (pos < CAP) buf[pos] = d;
        }
    }
    __syncthreads();
    const int n = sh_cnt;

    // ---- Phase 2: exact interpolated quantiles -> IQR bounds ------------
    float lb, ub;
    if (n > 0) {
        float nf = (float)(n - 1);
        float pos1 = 0.25f * nf;
        float pos3 = 0.75f * nf;
        int lo1 = (int)floorf(pos1), hi1 = (int)ceilf(pos1);
        int lo3 = (int)floorf(pos3), hi3 = (int)ceilf(pos3);
        float f1 = pos1 - (float)lo1;
        float f3 = pos3 - (float)lo3;

        float vlo1, vhi1, vlo3, vhi3;
        if (n <= CAP) {
            vlo1 = kth_from_buf(buf, n, lo1, hist, &sh_prefix, &sh_k, tid);
            vhi1 = (hi1 == lo1) ? vlo1
                 : kth_from_buf(buf, n, hi1, hist, &sh_prefix, &sh_k, tid);
            vlo3 = kth_from_buf(buf, n, lo3, hist, &sh_prefix, &sh_k, tid);
            vhi3 = (hi3 == lo3) ? vlo3
                 : kth_from_buf(buf, n, hi3, hist, &sh_prefix, &sh_k, tid);
        } else {
            vlo1 = kth_from_gmem(depth, ind, pid, lo1, hist, &sh_prefix, &sh_k, tid);
            vhi1 = (hi1 == lo1) ? vlo1
                 : kth_from_gmem(depth, ind, pid, hi1, hist, &sh_prefix, &sh_k, tid);
            vlo3 = kth_from_gmem(depth, ind, pid, lo3, hist, &sh_prefix, &sh_k, tid);
            vhi3 = (hi3 == lo3) ? vlo3
                 : kth_from_gmem(depth, ind, pid, hi3, hist, &sh_prefix, &sh_k, tid);
        }
        float q1 = vlo1 + (vhi1 - vlo1) * f1;
        float q3 = vlo3 + (vhi3 - vlo3) * f3;
        float iqr = q3 - q1;
        lb = q1 - 1.5f * iqr;
        ub = q3 + 1.5f * iqr;
    } else {
        lb = 1.0f;   // empty interval: keep nothing
        ub = 0.0f;
    }

    // ---- Phase 3a: zero this CTA's output slice --------------------------
    float* outb = out + (size_t)b * 3 * SEG + (size_t)p * (KK + 1);
    for (int j = tid; j < 3 * (KK + 1); j += NTHREADS) {
        int c = j / (KK + 1);
        int k = j - c * (KK + 1);
        outb[(size_t)c * SEG + k] = 0.0f;
    }
    __syncthreads();

    // ---- Phase 3b: raster-order compaction of kept points ---------------
    int running = 0;
    for (int base = 0; base < NPAD; base += NTHREADS) {
        int i = base + tid;
        bool keep = false;
        float d = 0.0f;
        if (i < NN) {
            d = depth[i];
            int pv = __float2int_rn(ind[i]);
            keep = (pv == pid) && (d > 3.0f) && (d >= lb) && (d <= ub);
        }
        unsigned bal = __ballot_sync(0xffffffffu, keep);
        int lane = tid & 31, warp = tid >> 5;
        int before = __popc(bal & ((1u << lane) - 1u));
        if (lane == 0) warp_sums[warp] = __popc(bal);
        __syncthreads();
        if (warp == 0) {
            int s = warp_sums[lane];
            #pragma unroll
            for (int off = 1; off < 32; off <<= 1) {
                int t = __shfl_up_sync(0xffffffffu, s, off);
                if (lane >= off) s += t;
            }
            warp_sums[lane] = s;   // inclusive scan of warp totals
        }
        __syncthreads();
        int excl = (warp == 0) ? 0 : warp_sums[warp - 1];
        int rank = running + excl + before;
        if (keep && rank < KK) {
            int x = i % WW;
            int y = i / WW;
            outb[rank]                   = xcam[x] * d;   // channel 0
            outb[SEG + rank]             = ycam[y] * d;   // channel 1
            outb[2 * (size_t)SEG + rank] = d;             // channel 2
        }
        running += warp_sums[31];
        __syncthreads();
    }

    // Presence flag -> slot K, channel 0 (channels 1,2 already zeroed)
    if (tid == 0 && running > 0) outb[KK] = 1.0f;
}

extern "C" void kernel_launch(void* const* d_in, const int* in_sizes, int n_in,
                              void* d_out, int out_size) {
    const float* in = (const float*)d_in[0];
    float* out = (float*)d_out;
    int B = in_sizes[0] / (3 * NN);
    pc_kernel<<<B * PP, NTHREADS>>>(in, out);
}

// round 3
// speedup vs baseline: 2.3605x; 2.3605x over previous
#include <cuda_runtime.h>

#define HH 150
#define WW 200
#define NN (HH*WW)          // 30000
#define KK 1024
#define PP 5
#define SEG (PP*(KK+1))     // 5125
#define CAP 4096
#define NTH 1024
#define FULL 0xffffffffu

struct Smem {
    float          buf[PP][CAP];        // gathered depths, raster order
    unsigned short pix[PP][CAP];        // pixel index of each gathered depth
    int            hist[10][256];       // 10 radix-select chains
    int            wsum[2][PP][32];     // double-buffered cross-warp scan
    unsigned       prefix[10];
    int            kkv[10];
    int            lorank[10];
    float          fracv[10];
    int            chain_ok[10];
    unsigned       cntLE[10];
    unsigned       minGT[10];
    int            nvals[PP];
    float          lbv[PP], ubv[PP];
    float          xcam[WW];
    float          ycam[HH];
    unsigned       gpfx;                // gmem-fallback select state
    int            gkk;
};

__device__ __forceinline__ int iscan32(int v) {
    int lane = threadIdx.x & 31;
    #pragma unroll
    for (int o = 1; o < 32; o <<= 1) {
        int t = __shfl_up_sync(FULL, v, o);
        if (lane >= o) v += t;
    }
    return v;
}

// Exact k-th smallest valid depth for person pid, reading from gmem.
// Slow fallback, only used if a person's point count exceeds CAP.
__device__ float kth_from_gmem(const float* __restrict__ depth,
                               const float* __restrict__ ind,
                               int pid, int k, Smem* sm, int tid) {
    __syncthreads();
    if (tid == 0) { sm->gpfx = 0u; sm->gkk = k; }
    __syncthreads();
    for (int shift = 24; shift >= 0; shift -= 8) {
        for (int j = tid; j < 256; j += NTH) sm->hist[0][j] = 0;
        __syncthreads();
        unsigned pfx = sm->gpfx;
        for (int i = tid; i < NN; i += NTH) {
            float d = depth[i];
            int pv = __float2int_rn(ind[i]);
            if (pv == pid && d > 3.0f) {
                unsigned key = __float_as_uint(d);
                bool match = (shift == 24) ||
                             ((key >> (shift + 8)) == (pfx >> (shift + 8)));
                if (match) atomicAdd(&sm->hist[0][(key >> shift) & 255], 1);
            }
        }
        __syncthreads();
        if (tid == 0) {
            int kk = sm->gkk, cum = 0, bsel = 0;
            for (int bb = 0; bb < 256; bb++) {
                int h = sm->hist[0][bb];
                if (kk < cum + h) { kk -= cum; bsel = bb; break; }
                cum += h;
            }
            sm->gkk = kk;
            sm->gpfx = pfx | ((unsigned)bsel << shift);
        }
        __syncthreads();
    }
    return __uint_as_float(sm->gpfx);
}

__global__ void __launch_bounds__(NTH, 1)
pc_kernel(const float* __restrict__ in, float* __restrict__ out) {
    extern __shared__ char smem_raw[];
    Smem* sm = reinterpret_cast<Smem*>(smem_raw);

    const int b    = blockIdx.x;
    const int tid  = threadIdx.x;
    const int lane = tid & 31;
    const int warp = tid >> 5;

    const float* depth = in + (size_t)b * 3 * NN;
    const float* ind   = depth + NN;
    float* outb = out + (size_t)b * 3 * SEG;

    // ---- ray tables (fp64 once, matching NumPy float64 promotion) -------
    {
        const double PI = 3.14159265358979323846;
        const double fxd = 200.0 / (2.0 * tan(81.0 * PI / 180.0 / 2.0));
        const double fyd = 150.0 / (2.0 * tan(59.0 * PI / 180.0 / 2.0));
        if (tid < WW) sm->xcam[tid] = (float)(((double)tid - 100.0) / fxd);
        if (tid < HH) sm->ycam[tid] = (float)(((double)tid - 75.0) / fyd);
    }

    // ---- zero this batch's output slice (independent stores, drain early)
    for (int j = tid; j < 3 * SEG; j += NTH) outb[j] = 0.0f;

    // ---- Phase 1: gather all 5 persons, raster order, scan compaction ---
    const float4* d4 = reinterpret_cast<const float4*>(depth);
    const float4* i4 = reinterpret_cast<const float4*>(ind);
    int run0 = 0, run1 = 0, run2 = 0, run3 = 0, run4 = 0;
    int bb = 0;
    __syncthreads();   // smem tables ready (wsum untouched yet)

    #pragma unroll 1
    for (int it = 0; it < 8; it++) {
        int vbase = it * NTH + tid;             // float4 index, NN/4 = 7500
        bool inb = vbase < NN / 4;
        float4 dd = inb ? d4[vbase] : make_float4(0, 0, 0, 0);
        float4 ii = inb ? i4[vbase] : make_float4(0, 0, 0, 0);
        float dv[4] = {dd.x, dd.y, dd.z, dd.w};
        float iv[4] = {ii.x, ii.y, ii.z, ii.w};
        int pe[4], lr[4];
        int c0 = 0, c1 = 0, c2 = 0, c3 = 0, c4 = 0;
        #pragma unroll
        for (int e = 0; e < 4; e++) {
            int pv = __float2int_rn(iv[e]);
            bool v = inb && (pv >= 1) && (pv <= PP) && (dv[e] > 3.0f);
            int p = v ? pv - 1 : -1;
            pe[e] = p;
            lr[e] = (p == 0) ? c0 : (p == 1) ? c1 : (p == 2) ? c2 : (p == 3) ? c3 : c4;
            c0 += (p == 0); c1 += (p == 1); c2 += (p == 2);
            c3 += (p == 3); c4 += (p == 4);
        }
        int s0 = iscan32(c0), s1 = iscan32(c1), s2 = iscan32(c2),
            s3 = iscan32(c3), s4 = iscan32(c4);
        if (lane == 31) {
            sm->wsum[bb][0][warp] = s0; sm->wsum[bb][1][warp] = s1;
            sm->wsum[bb][2][warp] = s2; sm->wsum[bb][3][warp] = s3;
            sm->wsum[bb][4][warp] = s4;
        }
        __syncthreads();
        if (warp < PP) {
            int s = sm->wsum[bb][warp][lane];
            sm->wsum[bb][warp][lane] = iscan32(s);
        }
        __syncthreads();
        int base0 = run0 + (warp ? sm->wsum[bb][0][warp - 1] : 0) + (s0 - c0);
        int base1 = run1 + (warp ? sm->wsum[bb][1][warp - 1] : 0) + (s1 - c1);
        int base2 = run2 + (warp ? sm->wsum[bb][2][warp - 1] : 0) + (s2 - c2);
        int base3 = run3 + (warp ? sm->wsum[bb][3][warp - 1] : 0) + (s3 - c3);
        int base4 = run4 + (warp ? sm->wsum[bb][4][warp - 1] : 0) + (s4 - c4);
        #pragma unroll
        for (int e = 0; e < 4; e++) {
            int p = pe[e];
            if (p >= 0) {
                int bp = (p == 0) ? base0 : (p == 1) ? base1 :
                         (p == 2) ? base2 : (p == 3) ? base3 : base4;
                int pos = bp + lr[e];
                if (pos < CAP) {
                    sm->buf[p][pos] = dv[e];
                    sm->pix[p][pos] = (unsigned short)(vbase * 4 + e);
                }
            }
        }
        run0 += sm->wsum[bb][0][31]; run1 += sm->wsum[bb][1][31];
        run2 += sm->wsum[bb][2][31]; run3 += sm->wsum[bb][3][31];
        run4 += sm->wsum[bb][4][31];
        bb ^= 1;
    }
    if (tid == 0) {
        sm->nvals[0] = run0; sm->nvals[1] = run1; sm->nvals[2] = run2;
        sm->nvals[3] = run3; sm->nvals[4] = run4;
    }
    __syncthreads();

    // ---- Phase 2 init: 10 chains (person x {q1,q3}) ----------------------
    if (tid < 10) {
        int p = tid >> 1;
        int np = sm->nvals[p];
        bool ok = (np > 0) && (np <= CAP);
        float qq = (tid & 1) ? 0.75f : 0.25f;
        float posq = ok ? qq * (float)(np - 1) : 0.0f;
        int lo = (int)floorf(posq);
        sm->fracv[tid]  = posq - (float)lo;
        sm->kkv[tid]    = lo;
        sm->lorank[tid] = lo;
        sm->prefix[tid] = 0u;
        sm->chain_ok[tid] = ok ? 1 : 0;
        sm->cntLE[tid] = 0u;
        sm->minGT[tid] = 0xFFFFFFFFu;
    }
    __syncthreads();

    // ---- Phase 2: 4 radix passes, all 10 chains in parallel -------------
    for (int shift = 24; shift >= 0; shift -= 8) {
        for (int j = tid; j < 10 * 256; j += NTH)
            (&sm->hist[0][0])[j] = 0;
        __syncthreads();
        for (int p = 0; p < PP; p++) {
            int np = sm->nvals[p];
            if (np > CAP) np = 0;                     // fallback handles it
            unsigned pf0 = sm->prefix[2 * p], pf1 = sm->prefix[2 * p + 1];
            for (int i = tid; i < np; i += NTH) {
                unsigned key = __float_as_uint(sm->buf[p][i]);
                int bkt = (key >> shift) & 255;
                bool m0 = (shift == 24) ||
                          ((key >> (shift + 8)) == (pf0 >> (shift + 8)));
                bool m1 = (shift == 24) ||
                          ((key >> (shift + 8)) == (pf1 >> (shift + 8)));
                if (m0) {
                    unsigned mm = __activemask();
                    unsigned peers = __match_any_sync(mm, bkt);
                    if ((__ffs(peers) - 1) == lane)
                        atomicAdd(&sm->hist[2 * p][bkt], __popc(peers));
                }
                if (m1) {
                    unsigned mm = __activemask();
                    unsigned peers = __match_any_sync(mm, bkt);
                    if ((__ffs(peers) - 1) == lane)
                        atomicAdd(&sm->hist[2 * p + 1][bkt], __popc(peers));
                }
            }
        }
        __syncthreads();
        if (warp < 10 && sm->chain_ok[warp]) {
            int q = warp;
            int loc[8], s = 0;
            #pragma unroll
            for (int m = 0; m < 8; m++) { loc[m] = sm->hist[q][lane * 8 + m]; s += loc[m]; }
            int incl = iscan32(s);
            int excl = incl - s;
            int k = sm->kkv[q];
            if (k >= excl && k < incl) {
                int rem = k - excl;
                int bsel = -1;
                #pragma unroll
                for (int m = 0; m < 8; m++) {
                    if (bsel < 0) {
                        if (rem < loc[m]) bsel = lane * 8 + m;
                        else rem -= loc[m];
                    }
                }
                sm->kkv[q] = rem;
                sm->prefix[q] |= (unsigned)bsel << shift;
            }
        }
        __syncthreads();
    }

    // ---- count(<= vlo) and min(> vlo) per chain (for vhi) ----------------
    for (int p = 0; p < PP; p++) {
        int np = sm->nvals[p];
        if (np <= 0 || np > CAP) continue;
        unsigned v0 = sm->prefix[2 * p], v1 = sm->prefix[2 * p + 1];
        int rounded = (np + NTH - 1) / NTH * NTH;
        for (int i = tid; i < rounded; i += NTH) {
            unsigned key = (i < np) ? __float_as_uint(sm->buf[p][i]) : 0xFFFFFFFFu;
            unsigned ble0 = __ballot_sync(FULL, key <= v0);
            unsigned ble1 = __ballot_sync(FULL, key <= v1);
            unsigned g0 = (key > v0) ? key : 0xFFFFFFFFu;
            unsigned g1 = (key > v1) ? key : 0xFFFFFFFFu;
            #pragma unroll
            for (int o = 16; o > 0; o >>= 1) {
                g0 = min(g0, __shfl_xor_sync(FULL, g0, o));
                g1 = min(g1, __shfl_xor_sync(FULL, g1, o));
            }
            if (lane == 0) {
                if (ble0) atomicAdd(&sm->cntLE[2 * p], (unsigned)__popc(ble0));
                if (ble1) atomicAdd(&sm->cntLE[2 * p + 1], (unsigned)__popc(ble1));
                atomicMin(&sm->minGT[2 * p], g0);
                atomicMin(&sm->minGT[2 * p + 1], g1);
            }
        }
    }
    __syncthreads();

    // ---- lb/ub per person -------------------------------------------------
    if (tid < PP) {
        int p = tid;
        int np = sm->nvals[p];
        if (np == 0) { sm->lbv[p] = 1.0f; sm->ubv[p] = 0.0f; }
        else if (np <= CAP) {
            float q[2];
            #pragma unroll
            for (int c = 0; c < 2; c++) {
                int ch = 2 * p + c;
                float vlo = __uint_as_float(sm->prefix[ch]);
                float f = sm->fracv[ch];
                if (f > 0.0f) {
                    float vhi = (sm->cntLE[ch] >= (unsigned)(sm->lorank[ch] + 2))
                              ? vlo : __uint_as_float(sm->minGT[ch]);
                    q[c] = vlo + (vhi - vlo) * f;
                } else q[c] = vlo;
            }
            float iqr = q[1] - q[0];
            sm->lbv[p] = q[0] - 1.5f * iqr;
            sm->ubv[p] = q[1] + 1.5f * iqr;
        }
        // np > CAP: set by fallback below
    }
    __syncthreads();

    // ---- overflow fallback (never hit for this shape, kept for rigor) ----
    for (int p = 0; p < PP; p++) {
        int np = sm->nvals[p];
        if (np <= CAP) continue;
        float nf = (float)(np - 1);
        float pos1 = 0.25f * nf, pos3 = 0.75f * nf;
        int lo1 = (int)floorf(pos1), hi1 = (int)ceilf(pos1);
        int lo3 = (int)floorf(pos3), hi3 = (int)ceilf(pos3);
        float f1 = pos1 - (float)lo1, f3 = pos3 - (float)lo3;
        float vlo1 = kth_from_gmem(depth, ind, p + 1, lo1, sm, tid);
        float vhi1 = (hi1 == lo1) ? vlo1 : kth_from_gmem(depth, ind, p + 1, hi1, sm, tid);
        float vlo3 = kth_from_gmem(depth, ind, p + 1, lo3, sm, tid);
        float vhi3 = (hi3 == lo3) ? vlo3 : kth_from_gmem(depth, ind, p + 1, hi3, sm, tid);
        if (tid == 0) {
            float q1 = vlo1 + (vhi1 - vlo1) * f1;
            float q3 = vlo3 + (vhi3 - vlo3) * f3;
            float iqr = q3 - q1;
            sm->lbv[p] = q1 - 1.5f * iqr;
            sm->ubv[p] = q3 + 1.5f * iqr;
        }
        __syncthreads();
    }

    // ---- Phase 3: raster-order compaction ---------------------------------
    for (int p = 0; p < PP; p++) {
        float lbp = sm->lbv[p], ubp = sm->ubv[p];
        float* outp = outb + p * (KK + 1);
        int np = sm->nvals[p];
        int run = 0, b2 = 0;
        if (np <= CAP) {
            for (int base = 0; base < np && run < KK; base += NTH) {
                int j = base + tid;
                bool keep = false; float d = 0.0f;
                if (j < np) {
                    d = sm->buf[p][j];
                    keep = (d >= lbp) && (d <= ubp);
                }
                unsigned bal = __ballot_sync(FULL, keep);
                if (lane == 0) sm->wsum[b2][0][warp] = __popc(bal);
                __syncthreads();
                if (warp == 0) {
                    int s = sm->wsum[b2][0][lane];
                    sm->wsum[b2][0][lane] = iscan32(s);
                }
                __syncthreads();
                int rank = run + (warp ? sm->wsum[b2][0][warp - 1] : 0)
                         + __popc(bal & ((1u << lane) - 1u));
                if (keep && rank < KK) {
                    int pxi = sm->pix[p][j];
                    int y = pxi / WW, x = pxi - y * WW;
                    outp[rank]           = sm->xcam[x] * d;
                    outp[SEG + rank]     = sm->ycam[y] * d;
                    outp[2 * SEG + rank] = d;
                }
                run += sm->wsum[b2][0][31];
                b2 ^= 1;
            }
        } else {
            // fallback: pixel pass with recomputed validity
            for (int base = 0; base < NN && run < KK; base += NTH) {
                int i = base + tid;
                bool keep = false; float d = 0.0f;
                if (i < NN) {
                    d = depth[i];
                    int pv = __float2int_rn(ind[i]);
                    keep = (pv == p + 1) && (d > 3.0f) && (d >= lbp) && (d <= ubp);
                }
                unsigned bal = __ballot_sync(FULL, keep);
                if (lane == 0) sm->wsum[b2][0][warp] = __popc(bal);
                __syncthreads();
                if (warp == 0) {
                    int s = sm->wsum[b2][0][lane];
                    sm->wsum[b2][0][lane] = iscan32(s);
                }
                __syncthreads();
                int rank = run + (warp ? sm->wsum[b2][0][warp - 1] : 0)
                         + __popc(bal & ((1u << lane) - 1u));
                if (keep && rank < KK) {
                    int y = i / WW, x = i - y * WW;
                    outp[rank]           = sm->xcam[x] * d;
                    outp[SEG + rank]     = sm->ycam[y] * d;
                    outp[2 * SEG + rank] = d;
                }
                run += sm->wsum[b2][0][31];
                b2 ^= 1;
            }
        }
        if (tid == 0 && run > 0) outp[KK] = 1.0f;
        __syncthreads();
    }
}

extern "C" void kernel_launch(void* const* d_in, const int* in_sizes, int n_in,
                              void* d_out, int out_size) {
    const float* in = (const float*)d_in[0];
    float* out = (float*)d_out;
    int B = in_sizes[0] / (3 * NN);
    size_t smem = sizeof(Smem);
    cudaFuncSetAttribute(pc_kernel, cudaFuncAttributeMaxDynamicSharedMemorySize,
                         (int)smem);
    pc_kernel<<<B, NTH, smem>>>(in, out);
}

// round 4
// speedup vs baseline: 2.8579x; 1.2107x over previous
#include <cuda_runtime.h>

#define HH 150
#define WW 200
#define NN (HH*WW)          // 30000
#define NV4 (NN/4)          // 7500
#define KK 1024
#define PP 5
#define SEG (PP*(KK+1))     // 5125
#define CAP 4096
#define T1 512
#define T2 512
#define FULL 0xffffffffu
#define MAXBP (4096*PP)

__device__ float g_lb[MAXBP];
__device__ float g_ub[MAXBP];

__device__ __forceinline__ int iscan32(int v) {
    int lane = threadIdx.x & 31;
    #pragma unroll
    for (int o = 1; o < 32; o <<= 1) {
        int t = __shfl_up_sync(FULL, v, o);
        if (lane >= o) v += t;
    }
    return v;
}

// ---------------------------------------------------------------------------
// Fallback exact k-th smallest reading from gmem (person count > CAP only;
// never hit for this input shape, kept for unconditional correctness).
// ---------------------------------------------------------------------------
__device__ float kth_from_gmem(const float* __restrict__ depth,
                               const float* __restrict__ ind,
                               int pid, int k, int* hist,
                               unsigned* gpfx, int* gkk, int tid) {
    __syncthreads();
    if (tid == 0) { *gpfx = 0u; *gkk = k; }
    __syncthreads();
    for (int shift = 24; shift >= 0; shift -= 8) {
        for (int j = tid; j < 256; j += T1) hist[j] = 0;
        __syncthreads();
        unsigned pfx = *gpfx;
        for (int i = tid; i < NN; i += T1) {
            float d = depth[i];
            int pv = __float2int_rn(ind[i]);
            if (pv == pid && d > 3.0f) {
                unsigned key = __float_as_uint(d);
                bool match = (shift == 24) ||
                             ((key >> (shift + 8)) == (pfx >> (shift + 8)));
                if (match) atomicAdd(&hist[(key >> shift) & 255], 1);
            }
        }
        __syncthreads();
        if (tid == 0) {
            int kk = *gkk, cum = 0, bsel = 0;
            for (int bb = 0; bb < 256; bb++) {
                int h = hist[bb];
                if (kk < cum + h) { kk -= cum; bsel = bb; break; }
                cum += h;
            }
            *gkk = kk;
            *gpfx = pfx | ((unsigned)bsel << shift);
        }
        __syncthreads();
    }
    return __uint_as_float(*gpfx);
}

// ---------------------------------------------------------------------------
// K1: one CTA per (b,p). Unordered gather of valid depths -> smem, then
// 2-chain parallel radix select -> lb/ub to global scratch.
// ---------------------------------------------------------------------------
__global__ void __launch_bounds__(T1)
k_bounds(const float* __restrict__ in) {
    const int blk = blockIdx.x;
    const int b = blk / PP, p = blk % PP, pid = p + 1;
    const int tid = threadIdx.x, lane = tid & 31, warp = tid >> 5;

    const float* depth = in + (size_t)b * 3 * NN;
    const float* ind   = depth + NN;

    __shared__ float buf[CAP];
    __shared__ int   hist[2][256];
    __shared__ int   s_cnt;
    __shared__ unsigned s_pfx[2];
    __shared__ int   s_k[2], s_lo[2];
    __shared__ float s_frac[2];
    __shared__ unsigned s_cntLE[2], s_minGT[2];
    __shared__ unsigned s_gpfx;
    __shared__ int   s_gkk;

    if (tid == 0) s_cnt = 0;
    __syncthreads();

    // ---- gather (order irrelevant for order statistics) ------------------
    const float4* d4 = reinterpret_cast<const float4*>(depth);
    const float4* i4 = reinterpret_cast<const float4*>(ind);
    #pragma unroll 1
    for (int it = 0; it < (NV4 + T1 - 1) / T1; it++) {
        int v = it * T1 + tid;
        bool inb = v < NV4;
        float4 dd = inb ? d4[v] : make_float4(0, 0, 0, 0);
        float4 ii = inb ? i4[v] : make_float4(0, 0, 0, 0);
        float dv[4] = {dd.x, dd.y, dd.z, dd.w};
        float iv[4] = {ii.x, ii.y, ii.z, ii.w};
        bool kv[4]; int c = 0;
        #pragma unroll
        for (int e = 0; e < 4; e++) {
            kv[e] = inb && (__float2int_rn(iv[e]) == pid) && (dv[e] > 3.0f);
            c += kv[e];
        }
        int incl = iscan32(c);
        int wtot = __shfl_sync(FULL, incl, 31);
        int base = 0;
        if (lane == 0 && wtot) base = atomicAdd(&s_cnt, wtot);
        base = __shfl_sync(FULL, base, 0);
        int off = base + incl - c;
        #pragma unroll
        for (int e = 0; e < 4; e++)
            if (kv[e]) { if (off < CAP) buf[off] = dv[e]; off++; }
    }
    __syncthreads();
    const int n = s_cnt;

    if (n == 0) {
        if (tid == 0) { g_lb[blk] = 1.0f; g_ub[blk] = 0.0f; }
        return;
    }

    if (n <= CAP) {
        if (tid < 2) {
            float posq = (tid ? 0.75f : 0.25f) * (float)(n - 1);
            int lo = (int)floorf(posq);
            s_lo[tid] = lo;
            s_frac[tid] = posq - (float)lo;
            s_k[tid] = lo;
            s_pfx[tid] = 0u;
            s_cntLE[tid] = 0u;
            s_minGT[tid] = 0xFFFFFFFFu;
        }
        __syncthreads();

        for (int shift = 24; shift >= 0; shift -= 8) {
            ((int*)hist)[tid] = 0;                        // 512 entries, 512 thr
            __syncthreads();
            unsigned pf0 = s_pfx[0], pf1 = s_pfx[1];
            bool same = (shift == 24) ||
                        ((pf0 >> (shift + 8)) == (pf1 >> (shift + 8)));
            for (int i = tid; i < n; i += T1) {
                unsigned key = __float_as_uint(buf[i]);
                int bkt = (key >> shift) & 255;
                bool m0 = (shift == 24) ||
                          ((key >> (shift + 8)) == (pf0 >> (shift + 8)));
                if (m0) {
                    unsigned mm = __activemask();
                    unsigned peers = __match_any_sync(mm, bkt);
                    if ((__ffs(peers) - 1) == lane)
                        atomicAdd(&hist[0][bkt], __popc(peers));
                }
                if (!same) {
                    bool m1 = ((key >> (shift + 8)) == (pf1 >> (shift + 8)));
                    if (m1) {
                        unsigned mm = __activemask();
                        unsigned peers = __match_any_sync(mm, bkt);
                        if ((__ffs(peers) - 1) == lane)
                            atomicAdd(&hist[1][bkt], __popc(peers));
                    }
                }
            }
            __syncthreads();
            if (warp < 2) {
                int hsel = same ? 0 : warp;
                int loc[8], s = 0;
                #pragma unroll
                for (int m = 0; m < 8; m++) {
                    loc[m] = hist[hsel][lane * 8 + m];
                    s += loc[m];
                }
                int incl = iscan32(s);
                int excl = incl - s;
                int k = s_k[warp];
                if (k >= excl && k < incl) {
                    int rem = k - excl, bsel = -1;
                    #pragma unroll
                    for (int m = 0; m < 8; m++) {
                        if (bsel < 0) {
                            if (rem < loc[m]) bsel = lane * 8 + m;
                            else rem -= loc[m];
                        }
                    }
                    s_k[warp] = rem;
                    s_pfx[warp] |= (unsigned)bsel << shift;
                }
            }
            __syncthreads();
        }

        // count(<= vlo) and min(> vlo) per chain, for interpolation partner
        unsigned v0 = s_pfx[0], v1 = s_pfx[1];
        int rounded = (n + T1 - 1) / T1 * T1;
        for (int i = tid; i < rounded; i += T1) {
            unsigned key = (i < n) ? __float_as_uint(buf[i]) : 0xFFFFFFFFu;
            unsigned ble0 = __ballot_sync(FULL, key <= v0);
            unsigned ble1 = __ballot_sync(FULL, key <= v1);
            unsigned g0 = (key > v0) ? key : 0xFFFFFFFFu;
            unsigned g1 = (key > v1) ? key : 0xFFFFFFFFu;
            #pragma unroll
            for (int o = 16; o > 0; o >>= 1) {
                g0 = min(g0, __shfl_xor_sync(FULL, g0, o));
                g1 = min(g1, __shfl_xor_sync(FULL, g1, o));
            }
            if (lane == 0) {
                if (ble0) atomicAdd(&s_cntLE[0], (unsigned)__popc(ble0));
                if (ble1) atomicAdd(&s_cntLE[1], (unsigned)__popc(ble1));
                atomicMin(&s_minGT[0], g0);
                atomicMin(&s_minGT[1], g1);
            }
        }
        __syncthreads();

        if (tid == 0) {
            float q[2];
            #pragma unroll
            for (int c = 0; c < 2; c++) {
                float vlo = __uint_as_float(s_pfx[c]);
                float f = s_frac[c];
                if (f > 0.0f) {
                    float vhi = (s_cntLE[c] >= (unsigned)(s_lo[c] + 2))
                              ? vlo : __uint_as_float(s_minGT[c]);
                    q[c] = vlo + (vhi - vlo) * f;
                } else q[c] = vlo;
            }
            float iqr = q[1] - q[0];
            g_lb[blk] = q[0] - 1.5f * iqr;
            g_ub[blk] = q[1] + 1.5f * iqr;
        }
        return;
    }

    // ---- overflow fallback (n > CAP) --------------------------------------
    {
        float nf = (float)(n - 1);
        float pos1 = 0.25f * nf, pos3 = 0.75f * nf;
        int lo1 = (int)floorf(pos1), hi1 = (int)ceilf(pos1);
        int lo3 = (int)floorf(pos3), hi3 = (int)ceilf(pos3);
        float f1 = pos1 - (float)lo1, f3 = pos3 - (float)lo3;
        float vlo1 = kth_from_gmem(depth, ind, pid, lo1, hist[0], &s_gpfx, &s_gkk, tid);
        float vhi1 = (hi1 == lo1) ? vlo1
                   : kth_from_gmem(depth, ind, pid, hi1, hist[0], &s_gpfx, &s_gkk, tid);
        float vlo3 = kth_from_gmem(depth, ind, pid, lo3, hist[0], &s_gpfx, &s_gkk, tid);
        float vhi3 = (hi3 == lo3) ? vlo3
                   : kth_from_gmem(depth, ind, pid, hi3, hist[0], &s_gpfx, &s_gkk, tid);
        if (tid == 0) {
            float q1 = vlo1 + (vhi1 - vlo1) * f1;
            float q3 = vlo3 + (vhi3 - vlo3) * f3;
            float iqr = q3 - q1;
            g_lb[blk] = q1 - 1.5f * iqr;
            g_ub[blk] = q3 + 1.5f * iqr;
        }
    }
}

// ---------------------------------------------------------------------------
// K2: one CTA per (b,p). Raster-order block-scan compaction straight to out,
// early exit at K points, tail-only zeroing.
// ---------------------------------------------------------------------------
__global__ void __launch_bounds__(T2)
k_compact(const float* __restrict__ in, float* __restrict__ out) {
    const int blk = blockIdx.x;
    const int b = blk / PP, p = blk % PP, pid = p + 1;
    const int tid = threadIdx.x, lane = tid & 31, warp = tid >> 5;

    const float* depth = in + (size_t)b * 3 * NN;
    const float* ind   = depth + NN;
    float* outp = out + (size_t)b * 3 * SEG + p * (KK + 1);

    __shared__ float xcam[WW];
    __shared__ float ycam[HH];
    __shared__ int   wsum[2][16];

    {   // ray tables (fp64 once; matches NumPy float64 promotion)
        const double PI = 3.14159265358979323846;
        const double fxd = 200.0 / (2.0 * tan(81.0 * PI / 180.0 / 2.0));
        const double fyd = 150.0 / (2.0 * tan(59.0 * PI / 180.0 / 2.0));
        if (tid < WW) xcam[tid] = (float)(((double)tid - 100.0) / fxd);
        if (tid < HH) ycam[tid] = (float)(((double)tid - 75.0) / fyd);
    }
    const float lb = g_lb[blk];
    const float ub = g_ub[blk];
    __syncthreads();

    const float4* d4 = reinterpret_cast<const float4*>(depth);
    const float4* i4 = reinterpret_cast<const float4*>(ind);
    int run = 0, bb = 0;
    const int NIT = (NV4 + T2 - 1) / T2;

    #pragma unroll 1
    for (int it = 0; it < NIT; it++) {
        int v = it * T2 + tid;
        bool inb = v < NV4;
        float4 dd = inb ? d4[v] : make_float4(0, 0, 0, 0);
        float4 ii = inb ? i4[v] : make_float4(0, 0, 0, 0);
        float dv[4] = {dd.x, dd.y, dd.z, dd.w};
        float iv[4] = {ii.x, ii.y, ii.z, ii.w};
        bool kv[4]; int c = 0;
        #pragma unroll
        for (int e = 0; e < 4; e++) {
            kv[e] = inb && (__float2int_rn(iv[e]) == pid) && (dv[e] > 3.0f)
                        && (dv[e] >= lb) && (dv[e] <= ub);
            c += kv[e];
        }
        int incl = iscan32(c);
        if (lane == 31) wsum[bb][warp] = incl;
        __syncthreads();
        if (warp == 0) {
            int s = (lane < 16) ? wsum[bb][lane] : 0;
            s = iscan32(s);
            if (lane < 16) wsum[bb][lane] = s;
        }
        __syncthreads();
        int r = run + (warp ? wsum[bb][warp - 1] : 0) + incl - c;
        #pragma unroll
        for (int e = 0; e < 4; e++) {
            if (kv[e]) {
                if (r < KK) {
                    int i = v * 4 + e;
                    int y = i / WW, x = i - y * WW;
                    outp[r]           = xcam[x] * dv[e];
                    outp[SEG + r]     = ycam[y] * dv[e];
                    outp[2 * SEG + r] = dv[e];
                }
                r++;
            }
        }
        run += wsum[bb][15];
        bb ^= 1;
        if (run >= KK) break;    // later pixels can only rank >= K
    }

    // tail zero + flag (ranks [0, min(run,K)) were each written exactly once)
    int runc = run < KK ? run : KK;
    int tail = KK + 1 - runc;
    for (int j = tid; j < 3 * tail; j += T2) {
        int c = j / tail;
        int k = runc + (j - c * tail);
        float vv = (c == 0 && k == KK && run > 0) ? 1.0f : 0.0f;
        outp[(size_t)c * SEG + k] = vv;
    }
}

extern "C" void kernel_launch(void* const* d_in, const int* in_sizes, int n_in,
                              void* d_out, int out_size) {
    const float* in = (const float*)d_in[0];
    float* out = (float*)d_out;
    int B = in_sizes[0] / (3 * NN);
    k_bounds<<<B * PP, T1>>>(in);
    k_compact<<<B * PP, T2>>>(in, out);
}